// round 8
// baseline (speedup 1.0000x reference)
#include <cuda_runtime.h>

#define NB 4
#define NC 21
#define HH 512
#define WW 512
#define PH 171
#define OH 169
#define NCCH 84
#define PP (PH*PH)
#define LLN (OH*OH)
#define BANDS 6
#define ROWSB 29
#define SRW 176
#define MSZ 192
#define ALPHA 5e-4f

__device__ float    g_pr[NCCH*PP];
__device__ unsigned g_lab[NB*PP];
__device__ float    g_mpart[NCCH*BANDS*MSZ];
__device__ float    g_mred[NCCH*MSZ];
__device__ float    g_ce[NB*PH];
__device__ int      g_cnt[NB*PH];

__device__ __forceinline__ float ftanh(float x){float r;asm("tanh.approx.f32 %0,%1;":"=f"(r):"f"(x));return r;}
__device__ __forceinline__ unsigned long long pk2(float lo, float hi){
    unsigned long long r; asm("mov.b64 %0,{%1,%2};":"=l"(r):"f"(lo),"f"(hi)); return r;
}
__device__ __forceinline__ void fma2(unsigned long long& d, unsigned long long a, unsigned long long b){
    asm("fma.rn.f32x2 %0,%1,%2,%0;":"+l"(d):"l"(a),"l"(b));
}
__device__ __forceinline__ float lo2(unsigned long long v){float a,b;asm("mov.b64 {%0,%1},%2;":"=f"(a),"=f"(b):"l"(v));return a;}
__device__ __forceinline__ float hi2(unsigned long long v){float a,b;asm("mov.b64 {%0,%1},%2;":"=f"(a),"=f"(b):"l"(v));return b;}

// ============ K1: CE + sigmoid/clip + 3x3 stride-3 maxpool + label bits ====
__global__ __launch_bounds__(512) void k_fused(const float* __restrict__ score,
                                               const int*   __restrict__ tg)
{
    __shared__ float    spx[NC*WW];
    __shared__ unsigned slab[WW];
    __shared__ float wce[16];
    __shared__ int   wcnt[16];
    __shared__ int   s_is64;

    const int oy = blockIdx.x, n = blockIdx.y, x = threadIdx.x;

    if (x == 0) {
        int is64 = 1;
        #pragma unroll
        for (int i = 0; i < 32; i++) if (tg[2*i+1] != 0) is64 = 0;
        s_is64 = is64;
    }
    __syncthreads();
    const bool is64 = (s_is64 != 0);
    const long long* tg64 = (const long long*)tg;

    float vpool[NC];
    #pragma unroll
    for (int cc = 0; cc < NC; cc++) vpool[cc] = 1e-6f;
    unsigned labbits = 0;
    float ce = 0.0f; int cnt = 0;

    const int r0 = 3*oy - 1;
    #pragma unroll
    for (int k = 0; k < 3; k++) {
        int r = r0 + k;
        if (r < 0 || r >= HH) continue;
        int pix = (n*HH + r)*WW + x;
        int t = is64 ? (int)tg64[pix] : tg[pix];
        bool mask21 = (t >= 0 && t < NC);
        bool valid  = (t != 255);
        const float* bp = score + ((size_t)(n*NC)*HH + r)*WW + x;

        float s0 = 0.f, s1 = 0.f, s2 = 0.f, xt = 0.f;
        #pragma unroll
        for (int cc = 0; cc < NC; cc++) {
            float v = __ldg(bp + (size_t)cc*(HH*WW));
            float e = __expf(v);
            if (cc % 3 == 0) s0 += e; else if (cc % 3 == 1) s1 += e; else s2 += e;
            if (cc == t) xt = v;
            float sg  = fmaf(ftanh(0.5f*v), 0.5f, 0.5f);
            float val = mask21 ? fminf(fmaxf(sg, 1e-6f), 1.0f) : 1e-6f;
            vpool[cc] = fmaxf(vpool[cc], val);
        }
        if (valid) { ce += __logf((s0 + s1) + s2) - xt; cnt++; }
        if (mask21) labbits |= (1u << t);
    }

    #pragma unroll
    for (int cc = 0; cc < NC; cc++) spx[cc*WW + x] = vpool[cc];
    slab[x] = labbits;

    #pragma unroll
    for (int o = 16; o; o >>= 1) {
        ce  += __shfl_xor_sync(0xffffffffu, ce, o);
        cnt += __shfl_xor_sync(0xffffffffu, cnt, o);
    }
    if ((x & 31) == 0) { wce[x >> 5] = ce; wcnt[x >> 5] = cnt; }
    __syncthreads();
    if (x == 0) {
        float s = 0.f; int cc2 = 0;
        #pragma unroll
        for (int i = 0; i < 16; i++) { s += wce[i]; cc2 += wcnt[i]; }
        g_ce[n*PH + oy] = s; g_cnt[n*PH + oy] = cc2;
    }

    for (int idx = x; idx < NC*PH; idx += 512) {
        int c = idx / PH, ox = idx - c*PH;
        int c0 = 3*ox - 1;
        float pm = -1e30f; unsigned ob = 0;
        #pragma unroll
        for (int j = 0; j < 3; j++) {
            int cc = c0 + j;
            if (cc >= 0 && cc < WW) { pm = fmaxf(pm, spx[c*WW + cc]); ob |= slab[cc]; }
        }
        g_pr[((n*NC + c)*PH + oy)*PH + ox] = pm;
        if (c == 0) g_lab[(n*PH + oy)*PH + ox] = ob;
    }
}

// ============ K2 helpers ===================================================
#define TRI(d,e) ((d)*9 - (d)*((d)-1)/2 + (e)-(d))

template<int D0, int ND>
__device__ __forceinline__ void lp_body(const float* sp, const float* sl,
                                        int nquad, int gt, float* red)
{
    unsigned long long acc[ND*5];
    #pragma unroll
    for (int i = 0; i < ND*5; i++) acc[i] = 0ull;
    const int Y0 = D0/3;

    for (int q = gt; q < nquad; q += 96) {
        int row = q / 43;
        int xq = (q - row*43)*4;
        float ap[3][8], al[2][8];
        #pragma unroll
        for (int y = 0; y < 3; y++) {
            const float4* p4 = (const float4*)(sp + (row+y)*SRW + xq);
            float4 u0 = p4[0], u1 = p4[1];
            ap[y][0]=u0.x; ap[y][1]=u0.y; ap[y][2]=u0.z; ap[y][3]=u0.w;
            ap[y][4]=u1.x; ap[y][5]=u1.y; ap[y][6]=u1.z; ap[y][7]=u1.w;
        }
        #pragma unroll
        for (int y = 0; y < 2; y++) {
            const float4* p4 = (const float4*)(sl + (row+Y0+y)*SRW + xq);
            float4 u0 = p4[0], u1 = p4[1];
            al[y][0]=u0.x; al[y][1]=u0.y; al[y][2]=u0.z; al[y][3]=u0.w;
            al[y][4]=u1.x; al[y][5]=u1.y; al[y][6]=u1.z; al[y][7]=u1.w;
        }
        int nv = 169 - xq;
        #pragma unroll
        for (int q2 = 0; q2 < 4; q2++) {
            if (q2 < nv) {
                unsigned long long prp[5];
                prp[0] = pk2(ap[0][q2+0], ap[0][q2+1]);
                prp[1] = pk2(ap[0][q2+2], ap[1][q2+0]);
                prp[2] = pk2(ap[1][q2+1], ap[1][q2+2]);
                prp[3] = pk2(ap[2][q2+0], ap[2][q2+1]);
                prp[4] = pk2(ap[2][q2+2], 0.f);
                #pragma unroll
                for (int dd = 0; dd < ND; dd++) {
                    const int d = D0 + dd;
                    float l = al[d/3 - Y0][q2 + d%3];
                    unsigned long long l2 = pk2(l, l);
                    #pragma unroll
                    for (int j = 0; j < 5; j++) fma2(acc[dd*5+j], l2, prp[j]);
                }
            }
        }
    }
    #pragma unroll
    for (int dd = 0; dd < ND; dd++)
        #pragma unroll
        for (int j = 0; j < 5; j++) {
            const int e = 2*j;
            red[(D0+dd)*9 + e] = lo2(acc[dd*5+j]);
            if (e + 1 < 9) red[(D0+dd)*9 + e + 1] = hi2(acc[dd*5+j]);
        }
}

__device__ __forceinline__ void sq_body(const float* S, int nquad, int gt, float* red)
{
    unsigned long long accT[25], accS[5];
    #pragma unroll
    for (int i = 0; i < 25; i++) accT[i] = 0ull;
    #pragma unroll
    for (int i = 0; i < 5; i++) accS[i] = 0ull;
    const unsigned long long ONE2 = pk2(1.f, 1.f);

    for (int q = gt; q < nquad; q += 96) {
        int row = q / 43;
        int xq = (q - row*43)*4;
        float a[3][8];
        #pragma unroll
        for (int y = 0; y < 3; y++) {
            const float4* p4 = (const float4*)(S + (row+y)*SRW + xq);
            float4 u0 = p4[0], u1 = p4[1];
            a[y][0]=u0.x; a[y][1]=u0.y; a[y][2]=u0.z; a[y][3]=u0.w;
            a[y][4]=u1.x; a[y][5]=u1.y; a[y][6]=u1.z; a[y][7]=u1.w;
        }
        int nv = 169 - xq;
        #pragma unroll
        for (int q2 = 0; q2 < 4; q2++) {
            if (q2 < nv) {
                float v[9];
                #pragma unroll
                for (int d = 0; d < 9; d++) v[d] = a[d/3][q2 + d%3];
                unsigned long long vpE[5] = {pk2(v[0],v[1]), pk2(v[2],v[3]), pk2(v[4],v[5]),
                                             pk2(v[6],v[7]), pk2(v[8],0.f)};
                unsigned long long vpO[4] = {pk2(v[1],v[2]), pk2(v[3],v[4]),
                                             pk2(v[5],v[6]), pk2(v[7],v[8])};
                #pragma unroll
                for (int j = 0; j < 5; j++) fma2(accS[j], vpE[j], ONE2);
                int k = 0;
                #pragma unroll
                for (int d = 0; d < 9; d++) {
                    unsigned long long d2 = pk2(v[d], v[d]);
                    if ((d & 1) == 0) {
                        #pragma unroll
                        for (int j = d/2; j < 5; j++) { fma2(accT[k], d2, vpE[j]); k++; }
                    } else {
                        #pragma unroll
                        for (int j = (d-1)/2; j < 4; j++) { fma2(accT[k], d2, vpO[j]); k++; }
                    }
                }
            }
        }
    }
    int k = 0;
    #pragma unroll
    for (int d = 0; d < 9; d++) {
        if ((d & 1) == 0) {
            #pragma unroll
            for (int j = d/2; j < 5; j++) {
                const int e = 2*j;
                red[TRI(d,e)] = lo2(accT[k]);
                if (e + 1 < 9) red[TRI(d,e+1)] = hi2(accT[k]);
                k++;
            }
        } else {
            #pragma unroll
            for (int j = (d-1)/2; j < 4; j++) {
                const int e = 2*j + 1;
                red[TRI(d,e)]   = lo2(accT[k]);
                red[TRI(d,e+1)] = hi2(accT[k]);
                k++;
            }
        }
    }
    #pragma unroll
    for (int j = 0; j < 5; j++) {
        red[45 + 2*j] = lo2(accS[j]);
        if (2*j + 1 < 9) red[45 + 2*j + 1] = hi2(accS[j]);
    }
}

template<int J0, int J1>
__device__ __forceinline__ void wred(float* red, float (*wbuf)[81], int warp, int lane)
{
    #pragma unroll
    for (int j = J0; j < J1; j++) {
        float v = red[j];
        #pragma unroll
        for (int o = 16; o; o >>= 1) v += __shfl_xor_sync(0xffffffffu, v, o);
        if (lane == (j & 31)) wbuf[warp][j] = v;
    }
}

// ============ K2: Gram moments via smem staging + f32x2 FMA ================
__global__ __launch_bounds__(384) void k_mom()
{
    __shared__ float sp[31*SRW];
    __shared__ float sl[31*SRW];
    __shared__ float wbuf[12][81];

    const int nc = blockIdx.x, band = blockIdx.y;
    const int n = nc / NC, c = nc - n*NC;
    const int tid = threadIdx.x;
    const int r0 = band*ROWSB;
    const int nin = min(31, PH - r0);

    for (int i = tid; i < 31*SRW; i += 384) {
        int r = i / SRW, x = i - r*SRW;
        float pv = 0.f, lv = 0.f;
        if (r < nin && x < PH) {
            int gi = (r0 + r)*PH + x;
            pv = g_pr[nc*PP + gi] - 0.5f;
            lv = ((g_lab[n*PP + gi] >> c) & 1u) ? 0.5f : -0.5f;
        }
        sp[i] = pv; sl[i] = lv;
    }
    __syncthreads();

    const int rows_out = min(ROWSB, OH - r0);
    const int nquad = rows_out * 43;
    const int grp = tid / 96;
    const int gt  = tid - grp*96;
    const int warp = tid >> 5, lane = tid & 31;

    float red[81];
    #pragma unroll
    for (int j = 0; j < 81; j++) red[j] = 0.f;

    if (grp == 0) {
        lp_body<0,5>(sp, sl, nquad, gt, red);
        wred<0,45>(red, wbuf, warp, lane);
    } else if (grp == 1) {
        lp_body<5,4>(sp, sl, nquad, gt, red);
        wred<45,81>(red, wbuf, warp, lane);
    } else if (grp == 2) {
        sq_body(sp, nquad, gt, red);
        wred<0,54>(red, wbuf, warp, lane);
    } else {
        sq_body(sl, nquad, gt, red);
        wred<0,54>(red, wbuf, warp, lane);
    }
    __syncthreads();

    // layout: [0..80]=S_lp, [81..125]=S_pp tri, [126..134]=s_pr,
    //         [135..179]=S_ll tri, [180..188]=s_la
    if (tid < 189) {
        int w0, lj;
        if (tid < 45)       { w0 = 0; lj = tid; }
        else if (tid < 81)  { w0 = 3; lj = tid; }
        else if (tid < 135) { w0 = 6; lj = tid - 81; }
        else                { w0 = 9; lj = tid - 135; }
        float s = wbuf[w0][lj] + wbuf[w0+1][lj] + wbuf[w0+2][lj];
        g_mpart[(nc*BANDS + band)*MSZ + tid] = s;
    }
}

// ============ K3: reduce + 9x9 linear algebra + final scalar ===============
__global__ __launch_bounds__(256) void k_final(float* __restrict__ out, int out_size)
{
    __shared__ float srmi[NCCH];
    __shared__ float rce[256];
    __shared__ int   rcn[256];
    const int tid = threadIdx.x;

    for (int i = tid; i < NCCH*189; i += 256) {
        int nc = i / 189, j = i - nc*189;
        float s = 0.f;
        #pragma unroll
        for (int b = 0; b < BANDS; b++) s += g_mpart[(nc*BANDS + b)*MSZ + j];
        g_mred[nc*MSZ + j] = s;
    }

    float cs = 0.f; int cc = 0;
    for (int i = tid; i < NB*PH; i += 256) { cs += g_ce[i]; cc += g_cnt[i]; }
    rce[tid] = cs; rcn[tid] = cc;
    __syncthreads();
    for (int o = 128; o; o >>= 1) {
        if (tid < o) { rce[tid] += rce[tid+o]; rcn[tid] += rcn[tid+o]; }
        __syncthreads();
    }

    if (tid < NCCH) {
        const float* m = g_mred + tid*MSZ;
        const float invL = 1.0f / (float)LLN;
        float clp[81], cpp[45], cll[45], spr[9], sla[9];
        #pragma unroll
        for (int d = 0; d < 9; d++) { spr[d] = m[126+d]; sla[d] = m[180+d]; }
        int k = 0;
        for (int d = 0; d < 9; d++)
            for (int e = d; e < 9; e++) {
                cpp[k] = m[81+k]  - spr[d]*spr[e]*invL + (d==e ? ALPHA : 0.0f);
                cll[k] = m[135+k] - sla[d]*sla[e]*invL;
                k++;
            }
        for (int d = 0; d < 9; d++)
            for (int e = 0; e < 9; e++)
                clp[d*9+e] = m[d*9+e] - sla[d]*spr[e]*invL;

        for (int j = 0; j < 9; j++) {
            float s = cpp[TRI(j,j)];
            for (int q = 0; q < j; q++) { float g = cpp[TRI(q,j)]; s -= g*g; }
            float gjj = sqrtf(fmaxf(s, 1e-20f));
            cpp[TRI(j,j)] = gjj;
            float inv = 1.0f / gjj;
            for (int i = j+1; i < 9; i++) {
                float t = cpp[TRI(j,i)];
                for (int q = 0; q < j; q++) t -= cpp[TRI(q,i)]*cpp[TRI(q,j)];
                cpp[TRI(j,i)] = t*inv;
            }
        }
        for (int d = 0; d < 9; d++)
            for (int i = 0; i < 9; i++) {
                float s = clp[d*9+i];
                for (int q = 0; q < i; q++) s -= cpp[TRI(q,i)]*clp[d*9+q];
                clp[d*9+i] = s / cpp[TRI(i,i)];
            }
        k = 0;
        for (int d = 0; d < 9; d++)
            for (int e = d; e < 9; e++) {
                float s = cll[k];
                for (int i = 0; i < 9; i++) s -= clp[d*9+i]*clp[e*9+i];
                if (d == e) s += ALPHA;
                cll[k] = s; k++;
            }
        float rmi = 0.0f;
        for (int j = 0; j < 9; j++) {
            float s = cll[TRI(j,j)];
            for (int q = 0; q < j; q++) { float g = cll[TRI(q,j)]; s -= g*g; }
            float gjj = sqrtf(fmaxf(s, 0.0f));
            cll[TRI(j,j)] = gjj;
            float inv = 1.0f / gjj;
            for (int i = j+1; i < 9; i++) {
                float t = cll[TRI(j,i)];
                for (int q = 0; q < j; q++) t -= cll[TRI(q,i)]*cll[TRI(q,j)];
                cll[TRI(j,i)] = t*inv;
            }
            rmi += logf(gjj + 1e-8f);
        }
        srmi[tid] = rmi;
    }
    __syncthreads();

    if (tid == 0) {
        float rs = 0.f;
        #pragma unroll
        for (int i = 0; i < NCCH; i++) rs += srmi[i];
        float normal = rce[0] / (float)rcn[0];
        float loss = 0.5f*normal + 0.5f*(rs / 36.0f);
        for (int i = 0; i < out_size; i++) out[i] = loss;
    }
}

extern "C" void kernel_launch(void* const* d_in, const int* in_sizes, int n_in,
                              void* d_out, int out_size)
{
    const float* score;
    const int*   tg;
    if (in_sizes[0] >= in_sizes[1]) { score = (const float*)d_in[0]; tg = (const int*)d_in[1]; }
    else                            { score = (const float*)d_in[1]; tg = (const int*)d_in[0]; }

    k_fused<<<dim3(PH, NB), 512>>>(score, tg);
    k_mom<<<dim3(NCCH, BANDS), 384>>>();
    k_final<<<1, 256>>>((float*)d_out, out_size);
}

// round 9
// speedup vs baseline: 1.1563x; 1.1563x over previous
#include <cuda_runtime.h>

#define NB 4
#define NC 21
#define HH 512
#define WW 512
#define PH 171
#define OH 169
#define NCCH 84
#define PP (PH*PH)
#define LLN (OH*OH)
#define SRW 176
#define RB 27
#define BD2 7
#define MSZ 192
#define ALPHA 5e-4f

__device__ float    g_pr[NCCH*PP];      // pooled clipped sigmoid − 0.5
__device__ unsigned g_lab[NB*PP];
__device__ float    g_mpart[NCCH*BD2*MSZ];
__device__ float    g_mred[NCCH*MSZ];
__device__ float    g_ce[NB*PH];
__device__ int      g_cnt[NB*PH];

__device__ __forceinline__ float ftanh(float x){float r;asm("tanh.approx.f32 %0,%1;":"=f"(r):"f"(x));return r;}

// ============ K1: CE + raw-score maxpool + sigmoid-after-pool + label bits ==
__global__ __launch_bounds__(512) void k_fused(const float* __restrict__ score,
                                               const int*   __restrict__ tg)
{
    __shared__ float    spx[NC*WW];
    __shared__ unsigned slab[WW];
    __shared__ float wce[16];
    __shared__ int   wcnt[16];
    __shared__ int   s_is64;

    const int oy = blockIdx.x, n = blockIdx.y, x = threadIdx.x;

    if (x == 0) {
        int is64 = 1;
        #pragma unroll
        for (int i = 0; i < 32; i++) if (tg[2*i+1] != 0) is64 = 0;
        s_is64 = is64;
    }
    __syncthreads();
    const bool is64 = (s_is64 != 0);
    const long long* tg64 = (const long long*)tg;

    float vpool[NC];                    // pooled RAW scores (masked -> -inf)
    #pragma unroll
    for (int cc = 0; cc < NC; cc++) vpool[cc] = -1e30f;
    unsigned labbits = 0;
    float ce = 0.0f; int cnt = 0;

    const int r0 = 3*oy - 1;
    #pragma unroll
    for (int k = 0; k < 3; k++) {
        int r = r0 + k;
        if (r < 0 || r >= HH) continue;
        int pix = (n*HH + r)*WW + x;
        int t = is64 ? (int)tg64[pix] : tg[pix];
        bool mask21 = (t >= 0 && t < NC);
        bool valid  = (t != 255);
        const float* bp = score + ((size_t)(n*NC)*HH + r)*WW + x;

        float s0 = 0.f, s1 = 0.f, s2 = 0.f, xt = 0.f;
        #pragma unroll
        for (int cc = 0; cc < NC; cc++) {
            float v = __ldg(bp + (size_t)cc*(HH*WW));
            float e = __expf(v);
            if (cc % 3 == 0) s0 += e; else if (cc % 3 == 1) s1 += e; else s2 += e;
            if (cc == t) xt = v;
            float vm = mask21 ? v : -1e30f;
            vpool[cc] = fmaxf(vpool[cc], vm);
        }
        if (valid) { ce += __logf((s0 + s1) + s2) - xt; cnt++; }
        if (mask21) labbits |= (1u << t);
    }

    #pragma unroll
    for (int cc = 0; cc < NC; cc++) spx[cc*WW + x] = vpool[cc];
    slab[x] = labbits;

    #pragma unroll
    for (int o = 16; o; o >>= 1) {
        ce  += __shfl_xor_sync(0xffffffffu, ce, o);
        cnt += __shfl_xor_sync(0xffffffffu, cnt, o);
    }
    if ((x & 31) == 0) { wce[x >> 5] = ce; wcnt[x >> 5] = cnt; }
    __syncthreads();
    if (x == 0) {
        float s = 0.f; int cc2 = 0;
        #pragma unroll
        for (int i = 0; i < 16; i++) { s += wce[i]; cc2 += wcnt[i]; }
        g_ce[n*PH + oy] = s; g_cnt[n*PH + oy] = cc2;
    }

    // finish pooling along x, THEN sigmoid+clip once per pooled cell
    for (int idx = x; idx < NC*PH; idx += 512) {
        int c = idx / PH, ox = idx - c*PH;
        int c0 = 3*ox - 1;
        float pm = -1e30f; unsigned ob = 0;
        #pragma unroll
        for (int j = 0; j < 3; j++) {
            int cc = c0 + j;
            if (cc >= 0 && cc < WW) { pm = fmaxf(pm, spx[c*WW + cc]); ob |= slab[cc]; }
        }
        float sg  = fmaf(ftanh(0.5f*pm), 0.5f, 0.5f);
        float val = fminf(fmaxf(sg, 1e-6f), 1.0f) - 0.5f;   // pre-shifted
        g_pr[((n*NC + c)*PH + oy)*PH + ox] = val;
        if (c == 0) g_lab[(n*PH + oy)*PH + ox] = ob;
    }
}

// ============ K2: Gram moments, 5 groups x 64 thr, scalar FFMA =============
#define TRI(d,e) ((d)*9 - (d)*((d)-1)/2 + (e)-(d))

__device__ __forceinline__ void load8(const float* p, float* a)
{
    float4 u0 = *(const float4*)p;
    float4 u1 = *(const float4*)(p + 4);
    a[0]=u0.x; a[1]=u0.y; a[2]=u0.z; a[3]=u0.w;
    a[4]=u1.x; a[5]=u1.y; a[6]=u1.z; a[7]=u1.w;
}

__global__ __launch_bounds__(320, 2) void k_mom()
{
    __shared__ float sp[29*SRW];
    __shared__ float sl[29*SRW];
    __shared__ float wbuf[10][54];

    const int nc = blockIdx.x, band = blockIdx.y;
    const int n = nc / NC, c = nc - n*NC;
    const int tid = threadIdx.x;
    const int r0 = band*RB;
    const int rows_out = min(RB, OH - r0);
    const int nin = rows_out + 2;

    for (int i = tid; i < 29*SRW; i += 320) {
        int r = i / SRW, x = i - r*SRW;
        float pv = 0.f, lv = 0.f;
        if (r < nin && x < PH) {
            int gi = (r0 + r)*PH + x;
            pv = g_pr[nc*PP + gi];
            lv = ((g_lab[n*PP + gi] >> c) & 1u) ? 0.5f : -0.5f;
        }
        sp[i] = pv; sl[i] = lv;
    }
    __syncthreads();

    const int grp = tid >> 6;         // 0,1,2 = lp dy; 3 = pp; 4 = ll
    const int gt  = tid & 63;
    const int warp = tid >> 5, lane = tid & 31;
    const int nq = rows_out*43;

    if (grp < 3) {
        const int dy = grp;
        float acc[27];
        #pragma unroll
        for (int i = 0; i < 27; i++) acc[i] = 0.f;

        int row = (gt >= 43) ? 1 : 0;
        int qx  = gt - (row ? 43 : 0);
        for (int q = gt; q < nq; q += 64) {
            const int xq = qx*4;
            float A[8], B[3][8];
            load8(sl + (row+dy)*SRW + xq, A);
            #pragma unroll
            for (int ey = 0; ey < 3; ey++) load8(sp + (row+ey)*SRW + xq, B[ey]);
            const int nv = 169 - xq;
            #pragma unroll
            for (int q2 = 0; q2 < 4; q2++) {
                if (q2 < nv) {
                    #pragma unroll
                    for (int dx = 0; dx < 3; dx++) {
                        float l = A[q2+dx];
                        #pragma unroll
                        for (int e = 0; e < 9; e++)
                            acc[dx*9+e] = fmaf(l, B[e/3][q2 + e%3], acc[dx*9+e]);
                    }
                }
            }
            qx += 21; row += 1;
            if (qx >= 43) { qx -= 43; row += 1; }
        }
        #pragma unroll
        for (int j = 0; j < 27; j++) {
            float v = acc[j];
            #pragma unroll
            for (int o = 16; o; o >>= 1) v += __shfl_xor_sync(0xffffffffu, v, o);
            if (lane == (j & 31)) wbuf[warp][j] = v;
        }
    } else {
        const float* S = (grp == 3) ? sp : sl;
        float accT[45], accS[9];
        #pragma unroll
        for (int i = 0; i < 45; i++) accT[i] = 0.f;
        #pragma unroll
        for (int i = 0; i < 9; i++) accS[i] = 0.f;

        int row = (gt >= 43) ? 1 : 0;
        int qx  = gt - (row ? 43 : 0);
        for (int q = gt; q < nq; q += 64) {
            const int xq = qx*4;
            float B[3][8];
            #pragma unroll
            for (int y = 0; y < 3; y++) load8(S + (row+y)*SRW + xq, B[y]);
            const int nv = 169 - xq;
            #pragma unroll
            for (int q2 = 0; q2 < 4; q2++) {
                if (q2 < nv) {
                    float v[9];
                    #pragma unroll
                    for (int d = 0; d < 9; d++) v[d] = B[d/3][q2 + d%3];
                    int k = 0;
                    #pragma unroll
                    for (int d = 0; d < 9; d++) {
                        accS[d] += v[d];
                        #pragma unroll
                        for (int e = d; e < 9; e++) { accT[k] = fmaf(v[d], v[e], accT[k]); k++; }
                    }
                }
            }
            qx += 21; row += 1;
            if (qx >= 43) { qx -= 43; row += 1; }
        }
        float red[54];
        #pragma unroll
        for (int k = 0; k < 45; k++) red[k] = accT[k];
        #pragma unroll
        for (int d = 0; d < 9; d++) red[45+d] = accS[d];
        #pragma unroll
        for (int j = 0; j < 54; j++) {
            float v = red[j];
            #pragma unroll
            for (int o = 16; o; o >>= 1) v += __shfl_xor_sync(0xffffffffu, v, o);
            if (lane == (j & 31)) wbuf[warp][j] = v;
        }
    }
    __syncthreads();

    // layout: [0..80]=S_lp (d*9+e), [81..125]=S_pp tri, [126..134]=s_pr,
    //         [135..179]=S_ll tri, [180..188]=s_la
    if (tid < 189) {
        int g, lj;
        if      (tid < 81)  { g = tid / 27; lj = tid - g*27; }
        else if (tid < 135) { g = 3; lj = tid - 81; }
        else                { g = 4; lj = tid - 135; }
        float s = wbuf[2*g][lj] + wbuf[2*g+1][lj];
        g_mpart[(nc*BD2 + band)*MSZ + tid] = s;
    }
}

// ============ K3: reduce + 9x9 linear algebra + final scalar ===============
__global__ __launch_bounds__(256) void k_final(float* __restrict__ out, int out_size)
{
    __shared__ float srmi[NCCH];
    __shared__ float rce[256];
    __shared__ int   rcn[256];
    const int tid = threadIdx.x;

    for (int i = tid; i < NCCH*189; i += 256) {
        int nc = i / 189, j = i - nc*189;
        float s = 0.f;
        #pragma unroll
        for (int b = 0; b < BD2; b++) s += g_mpart[(nc*BD2 + b)*MSZ + j];
        g_mred[nc*MSZ + j] = s;
    }

    float cs = 0.f; int cc = 0;
    for (int i = tid; i < NB*PH; i += 256) { cs += g_ce[i]; cc += g_cnt[i]; }
    rce[tid] = cs; rcn[tid] = cc;
    __syncthreads();
    for (int o = 128; o; o >>= 1) {
        if (tid < o) { rce[tid] += rce[tid+o]; rcn[tid] += rcn[tid+o]; }
        __syncthreads();
    }

    if (tid < NCCH) {
        const float* m = g_mred + tid*MSZ;
        const float invL = 1.0f / (float)LLN;
        float clp[81], cpp[45], cll[45], spr[9], sla[9];
        #pragma unroll
        for (int d = 0; d < 9; d++) { spr[d] = m[126+d]; sla[d] = m[180+d]; }
        int k = 0;
        for (int d = 0; d < 9; d++)
            for (int e = d; e < 9; e++) {
                cpp[k] = m[81+k]  - spr[d]*spr[e]*invL + (d==e ? ALPHA : 0.0f);
                cll[k] = m[135+k] - sla[d]*sla[e]*invL;
                k++;
            }
        for (int d = 0; d < 9; d++)
            for (int e = 0; e < 9; e++)
                clp[d*9+e] = m[d*9+e] - sla[d]*spr[e]*invL;

        for (int j = 0; j < 9; j++) {
            float s = cpp[TRI(j,j)];
            for (int q = 0; q < j; q++) { float g = cpp[TRI(q,j)]; s -= g*g; }
            float gjj = sqrtf(fmaxf(s, 1e-20f));
            cpp[TRI(j,j)] = gjj;
            float inv = 1.0f / gjj;
            for (int i = j+1; i < 9; i++) {
                float t = cpp[TRI(j,i)];
                for (int q = 0; q < j; q++) t -= cpp[TRI(q,i)]*cpp[TRI(q,j)];
                cpp[TRI(j,i)] = t*inv;
            }
        }
        for (int d = 0; d < 9; d++)
            for (int i = 0; i < 9; i++) {
                float s = clp[d*9+i];
                for (int q = 0; q < i; q++) s -= cpp[TRI(q,i)]*clp[d*9+q];
                clp[d*9+i] = s / cpp[TRI(i,i)];
            }
        k = 0;
        for (int d = 0; d < 9; d++)
            for (int e = d; e < 9; e++) {
                float s = cll[k];
                for (int i = 0; i < 9; i++) s -= clp[d*9+i]*clp[e*9+i];
                if (d == e) s += ALPHA;
                cll[k] = s; k++;
            }
        float rmi = 0.0f;
        for (int j = 0; j < 9; j++) {
            float s = cll[TRI(j,j)];
            for (int q = 0; q < j; q++) { float g = cll[TRI(q,j)]; s -= g*g; }
            float gjj = sqrtf(fmaxf(s, 0.0f));
            cll[TRI(j,j)] = gjj;
            float inv = 1.0f / gjj;
            for (int i = j+1; i < 9; i++) {
                float t = cll[TRI(j,i)];
                for (int q = 0; q < j; q++) t -= cll[TRI(q,i)]*cll[TRI(q,j)];
                cll[TRI(j,i)] = t*inv;
            }
            rmi += logf(gjj + 1e-8f);
        }
        srmi[tid] = rmi;
    }
    __syncthreads();

    if (tid == 0) {
        float rs = 0.f;
        #pragma unroll
        for (int i = 0; i < NCCH; i++) rs += srmi[i];
        float normal = rce[0] / (float)rcn[0];
        float loss = 0.5f*normal + 0.5f*(rs / 36.0f);
        for (int i = 0; i < out_size; i++) out[i] = loss;
    }
}

extern "C" void kernel_launch(void* const* d_in, const int* in_sizes, int n_in,
                              void* d_out, int out_size)
{
    const float* score;
    const int*   tg;
    if (in_sizes[0] >= in_sizes[1]) { score = (const float*)d_in[0]; tg = (const int*)d_in[1]; }
    else                            { score = (const float*)d_in[1]; tg = (const int*)d_in[0]; }

    k_fused<<<dim3(PH, NB), 512>>>(score, tg);
    k_mom<<<dim3(NCCH, BD2), 320>>>();
    k_final<<<1, 256>>>((float*)d_out, out_size);
}